// round 12
// baseline (speedup 1.0000x reference)
#include <cuda_runtime.h>
#include <cstdint>

#define NN 50000
#define EE 800000
#define HH 128
#define RR 8
#define SNB 196                       // ceil(NN/256) node blocks
#define AGGSZ ((size_t)RR * NN * HH)
#define HSZ   ((size_t)NN * HH)

// ---------------- scratch, duplicated per graph (no allocation allowed) -----------
__device__ float g_agg[2 * AGGSZ];
__device__ float g_hA[2 * HSZ];
__device__ float g_hB[2 * HSZ];
__device__ int   g_cnt[2 * NN * RR];
__device__ float g_invc[2 * NN * RR];
__device__ int   g_beg[2 * NN * RR];
__device__ int   g_cur[2 * NN * RR];
__device__ int   g_bsum[2 * SNB];
__device__ int   g_ep[2 * EE];
__device__ float g_wgt[2 * NN * RR];
__device__ float g_m[2 * 9 * HH];
__device__ float g_u[2 * HH];         // final per-graph embeddings (pre-bias)

// ---------------- tf32 mma (raw fp32 bits = RZ-truncated tf32) ----------------
__device__ __forceinline__ void mma_tf32(float* c, const unsigned* a, const unsigned* b) {
    asm volatile(
        "mma.sync.aligned.m16n8k8.row.col.f32.tf32.tf32.f32 "
        "{%0,%1,%2,%3}, {%4,%5,%6,%7}, {%8,%9}, {%0,%1,%2,%3};"
        : "+f"(c[0]), "+f"(c[1]), "+f"(c[2]), "+f"(c[3])
        : "r"(a[0]), "r"(a[1]), "r"(a[2]), "r"(a[3]), "r"(b[0]), "r"(b[1]));
}

// ---------------- cp.async helpers ----------------
__device__ __forceinline__ void cp16(uint32_t saddr, const void* gaddr) {
    asm volatile("cp.async.cg.shared.global [%0], [%1], 16;" :: "r"(saddr), "l"(gaddr));
}
__device__ __forceinline__ void cp_commit() {
    asm volatile("cp.async.commit_group;");
}
template <int N>
__device__ __forceinline__ void cp_wait() {
    asm volatile("cp.async.wait_group %0;" :: "n"(N));
}

// ---------------- preprocessing ----------------
__global__ void hist_kernel(const int* __restrict__ ei, const int* __restrict__ et,
                            int* __restrict__ cnt, int* __restrict__ bsum) {
    int e = blockIdx.x * blockDim.x + threadIdx.x;
    if (e < EE) {
        int dst = ei[EE + e];
        int r = et[e];
        atomicAdd(&cnt[dst * RR + r], 1);
        atomicAdd(&bsum[dst >> 8], 1);
    }
}

__global__ void expand_kernel(const int* __restrict__ cnt, const int* __restrict__ bsum,
                              int* __restrict__ beg, int* __restrict__ cur,
                              float* __restrict__ invc) {
    __shared__ int sh[256];
    __shared__ int s_base;
    int b = blockIdx.x;
    int tid = threadIdx.x;

    sh[tid] = (tid < b) ? bsum[tid] : 0;
    __syncthreads();
    for (int off = 128; off > 0; off >>= 1) {
        if (tid < off) sh[tid] += sh[tid + off];
        __syncthreads();
    }
    if (tid == 0) s_base = sh[0];
    __syncthreads();

    int i = b * 256 + tid;
    int cv[RR];
    int d = 0;
    if (i < NN) {
        int4 c0 = *(const int4*)&cnt[i * RR];
        int4 c1 = *(const int4*)&cnt[i * RR + 4];
        cv[0] = c0.x; cv[1] = c0.y; cv[2] = c0.z; cv[3] = c0.w;
        cv[4] = c1.x; cv[5] = c1.y; cv[6] = c1.z; cv[7] = c1.w;
        #pragma unroll
        for (int r = 0; r < RR; r++) d += cv[r];
    }
    sh[tid] = d;
    __syncthreads();
    for (int off = 1; off < 256; off <<= 1) {
        int t = (tid >= off) ? sh[tid - off] : 0;
        __syncthreads();
        sh[tid] += t;
        __syncthreads();
    }
    if (i < NN) {
        int c0 = s_base + sh[tid] - d;
        #pragma unroll
        for (int r = 0; r < RR; r++) {
            beg[i * RR + r] = c0;
            cur[i * RR + r] = c0;
            invc[i * RR + r] = 1.0f / (float)(cv[r] > 0 ? cv[r] : 1);
            c0 += cv[r];
        }
    }
}

// scatter edges into CSR AND accumulate per-src relation weights (merged passes)
__global__ void scatter_kernel(const int* __restrict__ ei, const int* __restrict__ et,
                               int* __restrict__ cur, const float* __restrict__ invc,
                               int* __restrict__ ep, float* __restrict__ wgt) {
    int e = blockIdx.x * blockDim.x + threadIdx.x;
    if (e < EE) {
        int src = ei[e];
        int dst = ei[EE + e];
        int r = et[e];
        int pos = atomicAdd(&cur[dst * RR + r], 1);
        ep[pos] = src;
        atomicAdd(&wgt[src * RR + r], invc[dst * RR + r]);
    }
}

// ---------------- aggregation: warp per (rel,node) --------------------------------
__global__ void agg_kernel(const float* __restrict__ X, const int* __restrict__ beg,
                           const int* __restrict__ cnt, const float* __restrict__ invc,
                           const int* __restrict__ ep, float* __restrict__ aggout) {
    int gw = (blockIdx.x * blockDim.x + threadIdx.x) >> 5;
    int lane = threadIdx.x & 31;
    if (gw >= NN * RR) return;
    int rel = gw / NN;
    int node = gw - rel * NN;

    int comb = node * RR + rel;
    int b = beg[comb];
    int c = cnt[comb];
    float4 a = make_float4(0.f, 0.f, 0.f, 0.f);
    for (int e = b; e < b + c; e++) {
        int src = ep[e];
        float4 v = ((const float4*)(X + (size_t)src * HH))[lane];
        a.x += v.x; a.y += v.y; a.z += v.z; a.w += v.w;
    }
    float w = invc[comb];
    a.x *= w; a.y *= w; a.z *= w; a.w *= w;
    ((float4*)(aggout + ((size_t)rel * NN + node) * HH))[lane] = a;
}

// ---------------- tf32 tensor-core GEMM, cp.async double-buffered (round-10 cfg) --
#define BM 128
#define GBLK ((NN + BM - 1) / BM)
#define APAD 36
#define BPAD 136
#define ASZ (BM * APAD)
#define BSZ (32 * BPAD)
#define GSMEM (2 * (ASZ + BSZ) * 4)

__global__ __launch_bounds__(256) void gemm_kernel(
    const float* __restrict__ X, const float* __restrict__ Agg,
    const float* __restrict__ W, const float* __restrict__ root,
    const float* __restrict__ bias, float* __restrict__ out)
{
    extern __shared__ float smem[];
    uint32_t sbase = (uint32_t)__cvta_generic_to_shared(smem);

    int tid  = threadIdx.x;
    int warp = tid >> 5;
    int lane = tid & 31;
    int gID  = lane >> 2;
    int tig  = lane & 3;
    int wrow = (warp & 3) * 32;
    int wcol = (warp >> 2) * 64;
    int m0   = blockIdx.x * BM;

    int arow = tid >> 3, aq = (tid & 7) * 4;
    int bkr  = tid >> 5, bnq = (tid & 31) * 4;

    float c[2][8][4];
    #pragma unroll
    for (int mt = 0; mt < 2; mt++)
        #pragma unroll
        for (int nt = 0; nt < 8; nt++)
            #pragma unroll
            for (int q = 0; q < 4; q++) c[mt][nt][q] = 0.f;

    auto stage = [&](int ch, int buf) {
        int rel = ch >> 2, kc = ch & 3;
        const float* Wp   = (rel < RR) ? (W + (size_t)rel * HH * HH) : root;
        const float* Asrc = (rel < RR) ? (Agg + (size_t)rel * NN * HH) : X;
        uint32_t abase = sbase + (uint32_t)(buf * ASZ) * 4;
        uint32_t bbase = sbase + (uint32_t)(2 * ASZ + buf * BSZ) * 4;
        #pragma unroll
        for (int it = 0; it < 4; it++) {
            int row = arow + it * 32;
            int gm  = m0 + row; if (gm > NN - 1) gm = NN - 1;
            cp16(abase + (uint32_t)(row * APAD + aq) * 4,
                 Asrc + (size_t)gm * HH + kc * 32 + aq);
            int kr = bkr + it * 8;
            cp16(bbase + (uint32_t)(kr * BPAD + bnq) * 4,
                 Wp + (size_t)(kc * 32 + kr) * HH + bnq);
        }
        cp_commit();
    };

    stage(0, 0);

    for (int ch = 0; ch < 36; ch++) {
        int buf = ch & 1;
        if (ch < 35) { stage(ch + 1, buf ^ 1); cp_wait<1>(); }
        else         { cp_wait<0>(); }
        __syncthreads();

        const float* As = smem + buf * ASZ;
        const float* Bs = smem + 2 * ASZ + buf * BSZ;

        #pragma unroll
        for (int ks = 0; ks < 4; ks++) {
            int kb = ks * 8;
            unsigned b[8][2];
            #pragma unroll
            for (int nt = 0; nt < 8; nt++) {
                int col = wcol + nt * 8 + gID;
                b[nt][0] = __float_as_uint(Bs[(kb + tig) * BPAD + col]);
                b[nt][1] = __float_as_uint(Bs[(kb + tig + 4) * BPAD + col]);
            }
            unsigned a[2][4];
            #pragma unroll
            for (int mt = 0; mt < 2; mt++) {
                int r = wrow + mt * 16 + gID;
                a[mt][0] = __float_as_uint(As[r * APAD + kb + tig]);
                a[mt][1] = __float_as_uint(As[(r + 8) * APAD + kb + tig]);
                a[mt][2] = __float_as_uint(As[r * APAD + kb + tig + 4]);
                a[mt][3] = __float_as_uint(As[(r + 8) * APAD + kb + tig + 4]);
            }
            #pragma unroll
            for (int mt = 0; mt < 2; mt++)
                #pragma unroll
                for (int nt = 0; nt < 8; nt++)
                    mma_tf32(c[mt][nt], a[mt], b[nt]);
        }
        __syncthreads();
    }

    #pragma unroll
    for (int mt = 0; mt < 2; mt++) {
        int r0 = m0 + wrow + mt * 16 + gID;
        int r1 = r0 + 8;
        #pragma unroll
        for (int nt = 0; nt < 8; nt++) {
            int col = wcol + nt * 8 + 2 * tig;
            float b0 = bias[col], b1 = bias[col + 1];
            float v0 = fmaxf(c[mt][nt][0] + b0, 0.f);
            float v1 = fmaxf(c[mt][nt][1] + b1, 0.f);
            float v2 = fmaxf(c[mt][nt][2] + b0, 0.f);
            float v3 = fmaxf(c[mt][nt][3] + b1, 0.f);
            if (r0 < NN) *(float2*)(out + (size_t)r0 * HH + col) = make_float2(v0, v1);
            if (r1 < NN) *(float2*)(out + (size_t)r1 * HH + col) = make_float2(v2, v3);
        }
    }
}

// ---------------- collapsed layer-2: all 9 column sums in ONE pass over hB --------
#define WS_BLOCKS 148
__global__ void wsum_kernel(const float* __restrict__ hB, const float* __restrict__ wgt,
                            float* __restrict__ m) {
    __shared__ float sw[256 * RR];
    int tid = threadIdx.x;             // 128 threads = columns
    int rowsPer = (NN + gridDim.x - 1) / gridDim.x;
    int r0 = blockIdx.x * rowsPer;
    int r1 = min(NN, r0 + rowsPer);

    float acc[9];
    #pragma unroll
    for (int s = 0; s < 9; s++) acc[s] = 0.f;

    for (int base = r0; base < r1; base += 256) {
        int nrows = min(256, r1 - base);
        for (int idx = tid * 4; idx < nrows * RR; idx += 128 * 4)
            *(float4*)&sw[idx] = *(const float4*)&wgt[base * RR + idx];
        __syncthreads();
        for (int j = 0; j < nrows; j++) {
            float v = hB[(size_t)(base + j) * HH + tid];
            acc[8] += v;
            #pragma unroll
            for (int r = 0; r < RR; r++) acc[r] += sw[j * RR + r] * v;
        }
        __syncthreads();
    }
    #pragma unroll
    for (int s = 0; s < 9; s++) atomicAdd(&m[s * HH + tid], acc[s]);
}

// ---------------- layer-3 GEMV (9 blocks): u += (1/N) * m_slot @ W_slot ----------
__global__ void gemv_kernel(const float* __restrict__ W, const float* __restrict__ root,
                            const float* __restrict__ mIn, float* __restrict__ uo) {
    int slot = blockIdx.x;
    int tid = threadIdx.x;             // 128
    const float* Wp = (slot < RR) ? (W + (size_t)slot * HH * HH) : root;
    __shared__ float m[HH];
    m[tid] = mIn[slot * HH + tid];
    __syncthreads();
    float acc = 0.f;
    #pragma unroll 8
    for (int k = 0; k < HH; k++)
        acc += m[k] * Wp[k * HH + tid];
    atomicAdd(&uo[tid], acc * (1.0f / (float)NN));
}

// ---------------- final MLP head (bias of layer-3 folded in here) ----------------
__global__ void fcl_kernel(const float* __restrict__ bias2,
                           const float* __restrict__ fc1w, const float* __restrict__ fc1b,
                           const float* __restrict__ fc2w, const float* __restrict__ fc2b,
                           float* __restrict__ out) {
    __shared__ float h[2 * HH];
    __shared__ float red[HH];
    int tid = threadIdx.x;
    if (tid < 2 * HH) h[tid] = g_u[tid] + bias2[tid & 127];
    __syncthreads();
    if (tid < HH) {
        float y = fc1b[tid];
        for (int k = 0; k < 2 * HH; k++) y += h[k] * fc1w[k * HH + tid];
        y = fmaxf(y, 0.f);
        red[tid] = y * fc2w[tid];
    }
    __syncthreads();
    for (int off = 64; off > 0; off >>= 1) {
        if (tid < off) red[tid] += red[tid + off];
        __syncthreads();
    }
    if (tid == 0) out[0] = red[0] + fc2b[0];
}

// ---------------- host orchestration: two independent graph chains, 2 streams ----
extern "C" void kernel_launch(void* const* d_in, const int* in_sizes, int n_in,
                              void* d_out, int out_size) {
    const float* x1  = (const float*)d_in[0];
    const int*   ei1 = (const int*)d_in[1];
    const int*   et1 = (const int*)d_in[2];
    const float* x2  = (const float*)d_in[3];
    const int*   ei2 = (const int*)d_in[4];
    const int*   et2 = (const int*)d_in[5];
    const float* Wl[3]    = {(const float*)d_in[6],  (const float*)d_in[9],  (const float*)d_in[12]};
    const float* rootl[3] = {(const float*)d_in[7],  (const float*)d_in[10], (const float*)d_in[13]};
    const float* biasl[3] = {(const float*)d_in[8],  (const float*)d_in[11], (const float*)d_in[14]};
    const float* fc1w = (const float*)d_in[15];
    const float* fc1b = (const float*)d_in[16];
    const float* fc2w = (const float*)d_in[17];
    const float* fc2b = (const float*)d_in[18];

    static cudaStream_t sB = nullptr;
    static cudaEvent_t evF = nullptr, evJ = nullptr;
    if (!sB) {
        cudaStreamCreateWithFlags(&sB, cudaStreamNonBlocking);
        cudaEventCreateWithFlags(&evF, cudaEventDisableTiming);
        cudaEventCreateWithFlags(&evJ, cudaEventDisableTiming);
        cudaFuncSetAttribute(gemm_kernel, cudaFuncAttributeMaxDynamicSharedMemorySize, GSMEM);
    }

    void *agg_p, *hA_p, *hB_p, *cnt_p, *invc_p, *beg_p, *cur_p, *bsum_p, *ep_p, *wgt_p, *m_p, *u_p;
    cudaGetSymbolAddress(&agg_p, g_agg);
    cudaGetSymbolAddress(&hA_p, g_hA);
    cudaGetSymbolAddress(&hB_p, g_hB);
    cudaGetSymbolAddress(&cnt_p, g_cnt);
    cudaGetSymbolAddress(&invc_p, g_invc);
    cudaGetSymbolAddress(&beg_p, g_beg);
    cudaGetSymbolAddress(&cur_p, g_cur);
    cudaGetSymbolAddress(&bsum_p, g_bsum);
    cudaGetSymbolAddress(&ep_p, g_ep);
    cudaGetSymbolAddress(&wgt_p, g_wgt);
    cudaGetSymbolAddress(&m_p, g_m);
    cudaGetSymbolAddress(&u_p, g_u);

    const float* xs[2]  = {x1, x2};
    const int*   eis[2] = {ei1, ei2};
    const int*   ets[2] = {et1, et2};

    int aggBlocks = (NN * RR * 32 + 255) / 256;
    int eBlocks   = (EE + 255) / 256;

    cudaMemsetAsync(u_p, 0, 2 * HH * sizeof(float), 0);
    cudaEventRecord(evF, 0);
    cudaStreamWaitEvent(sB, evF, 0);

    for (int g = 0; g < 2; g++) {
        cudaStream_t s = (g == 0) ? (cudaStream_t)0 : sB;
        // per-graph scratch slices
        float* agg  = (float*)agg_p  + (size_t)g * AGGSZ;
        float* hA   = (float*)hA_p   + (size_t)g * HSZ;
        float* hB   = (float*)hB_p   + (size_t)g * HSZ;
        int*   cnt  = (int*)cnt_p    + (size_t)g * NN * RR;
        float* invc = (float*)invc_p + (size_t)g * NN * RR;
        int*   beg  = (int*)beg_p    + (size_t)g * NN * RR;
        int*   cur  = (int*)cur_p    + (size_t)g * NN * RR;
        int*   bsum = (int*)bsum_p   + (size_t)g * SNB;
        int*   ep   = (int*)ep_p     + (size_t)g * EE;
        float* wgt  = (float*)wgt_p  + (size_t)g * NN * RR;
        float* m    = (float*)m_p    + (size_t)g * 9 * HH;
        float* u    = (float*)u_p    + (size_t)g * HH;

        cudaMemsetAsync(cnt,  0, NN * RR * sizeof(int), s);
        cudaMemsetAsync(bsum, 0, SNB * sizeof(int), s);
        cudaMemsetAsync(wgt,  0, NN * RR * sizeof(float), s);
        cudaMemsetAsync(m,    0, 9 * HH * sizeof(float), s);

        hist_kernel<<<eBlocks, 256, 0, s>>>(eis[g], ets[g], cnt, bsum);
        expand_kernel<<<SNB, 256, 0, s>>>(cnt, bsum, beg, cur, invc);
        scatter_kernel<<<eBlocks, 256, 0, s>>>(eis[g], ets[g], cur, invc, ep, wgt);

        // layer 0: x -> hA
        agg_kernel<<<aggBlocks, 256, 0, s>>>(xs[g], beg, cnt, invc, ep, agg);
        gemm_kernel<<<GBLK, 256, GSMEM, s>>>(xs[g], agg, Wl[0], rootl[0], biasl[0], hA);
        // layer 1: hA -> hB
        agg_kernel<<<aggBlocks, 256, 0, s>>>(hA, beg, cnt, invc, ep, agg);
        gemm_kernel<<<GBLK, 256, GSMEM, s>>>(hA, agg, Wl[1], rootl[1], biasl[1], hB);
        // layers 2+3 collapsed: weighted column sums of hB, then GEMV
        wsum_kernel<<<WS_BLOCKS, 128, 0, s>>>(hB, wgt, m);
        gemv_kernel<<<9, 128, 0, s>>>(Wl[2], rootl[2], m, u);
    }

    cudaEventRecord(evJ, sB);
    cudaStreamWaitEvent((cudaStream_t)0, evJ, 0);
    fcl_kernel<<<1, 256>>>(biasl[2], fc1w, fc1b, fc2w, fc2b, (float*)d_out);
}

// round 13
// speedup vs baseline: 1.0273x; 1.0273x over previous
#include <cuda_runtime.h>
#include <cstdint>

#define NN 50000
#define EE 800000
#define HH 128
#define RR 8
#define SNB 196                       // ceil(NN/256) node blocks

// ---------------- scratch (device globals; no allocation allowed) ----------------
__device__ float g_agg[(size_t)RR * NN * HH];  // [rel][N][128] per-relation neighbor means
__device__ float g_hA[(size_t)NN * HH];
__device__ float g_hB[(size_t)NN * HH];
__device__ float g_part[2][(size_t)NN * HH];   // split-K partial outputs
__device__ int   g_cnt[NN * RR];
__device__ float g_invc[NN * RR];
__device__ int   g_beg[NN * RR];
__device__ int   g_cur[NN * RR];
__device__ int   g_bsum[SNB];
__device__ int   g_ep[EE];            // src node id, CSR-sorted by (dst, etype)
__device__ float g_wgt[NN * RR];      // w_r[j] = sum over edges (j->n, type r) of invc[n,r]
__device__ float g_m[9 * HH];         // column sums: slots 0..7 weighted, 8 = plain hB sum
__device__ float g_u[2 * HH];         // final per-graph embeddings (pre-bias)

// ---------------- tf32 mma (raw fp32 bits = RZ-truncated tf32) ----------------
__device__ __forceinline__ void mma_tf32(float* c, const unsigned* a, const unsigned* b) {
    asm volatile(
        "mma.sync.aligned.m16n8k8.row.col.f32.tf32.tf32.f32 "
        "{%0,%1,%2,%3}, {%4,%5,%6,%7}, {%8,%9}, {%0,%1,%2,%3};"
        : "+f"(c[0]), "+f"(c[1]), "+f"(c[2]), "+f"(c[3])
        : "r"(a[0]), "r"(a[1]), "r"(a[2]), "r"(a[3]), "r"(b[0]), "r"(b[1]));
}

// ---------------- cp.async helpers ----------------
__device__ __forceinline__ void cp16(uint32_t saddr, const void* gaddr) {
    asm volatile("cp.async.cg.shared.global [%0], [%1], 16;" :: "r"(saddr), "l"(gaddr));
}
__device__ __forceinline__ void cp_commit() {
    asm volatile("cp.async.commit_group;");
}
template <int N>
__device__ __forceinline__ void cp_wait() {
    asm volatile("cp.async.wait_group %0;" :: "n"(N));
}

// ---------------- preprocessing ----------------
__global__ void hist_kernel(const int* __restrict__ ei, const int* __restrict__ et) {
    int e = blockIdx.x * blockDim.x + threadIdx.x;
    if (e < EE) {
        int dst = ei[EE + e];
        int r = et[e];
        atomicAdd(&g_cnt[dst * RR + r], 1);
        atomicAdd(&g_bsum[dst >> 8], 1);
    }
}

// 196 blocks x 256: predecessor prefix over g_bsum + local node scan -> beg/cur/invc
__global__ void expand_kernel() {
    __shared__ int sh[256];
    __shared__ int s_base;
    int b = blockIdx.x;
    int tid = threadIdx.x;

    sh[tid] = (tid < b) ? g_bsum[tid] : 0;
    __syncthreads();
    for (int off = 128; off > 0; off >>= 1) {
        if (tid < off) sh[tid] += sh[tid + off];
        __syncthreads();
    }
    if (tid == 0) s_base = sh[0];
    __syncthreads();

    int i = b * 256 + tid;
    int cv[RR];
    int d = 0;
    if (i < NN) {
        int4 c0 = *(const int4*)&g_cnt[i * RR];
        int4 c1 = *(const int4*)&g_cnt[i * RR + 4];
        cv[0] = c0.x; cv[1] = c0.y; cv[2] = c0.z; cv[3] = c0.w;
        cv[4] = c1.x; cv[5] = c1.y; cv[6] = c1.z; cv[7] = c1.w;
        #pragma unroll
        for (int r = 0; r < RR; r++) d += cv[r];
    }
    sh[tid] = d;
    __syncthreads();
    for (int off = 1; off < 256; off <<= 1) {
        int t = (tid >= off) ? sh[tid - off] : 0;
        __syncthreads();
        sh[tid] += t;
        __syncthreads();
    }
    if (i < NN) {
        int c0 = s_base + sh[tid] - d;
        #pragma unroll
        for (int r = 0; r < RR; r++) {
            g_beg[i * RR + r] = c0;
            g_cur[i * RR + r] = c0;
            g_invc[i * RR + r] = 1.0f / (float)(cv[r] > 0 ? cv[r] : 1);
            c0 += cv[r];
        }
    }
}

// scatter edges into CSR AND accumulate per-src relation weights (merged passes)
__global__ void scatter_kernel(const int* __restrict__ ei, const int* __restrict__ et) {
    int e = blockIdx.x * blockDim.x + threadIdx.x;
    if (e < EE) {
        int src = ei[e];
        int dst = ei[EE + e];
        int r = et[e];
        int pos = atomicAdd(&g_cur[dst * RR + r], 1);
        g_ep[pos] = src;
        atomicAdd(&g_wgt[src * RR + r], g_invc[dst * RR + r]);
    }
}

// ---------------- aggregation: warp per (rel,node); writes g_agg[rel][N][128] -----
__global__ void agg_kernel(const float* __restrict__ X) {
    int gw = (blockIdx.x * blockDim.x + threadIdx.x) >> 5;
    int lane = threadIdx.x & 31;
    if (gw >= NN * RR) return;
    int rel = gw / NN;
    int node = gw - rel * NN;

    int comb = node * RR + rel;
    int b = g_beg[comb];
    int c = g_cnt[comb];
    float4 a = make_float4(0.f, 0.f, 0.f, 0.f);
    for (int e = b; e < b + c; e++) {
        int src = g_ep[e];
        float4 v = ((const float4*)(X + (size_t)src * HH))[lane];
        a.x += v.x; a.y += v.y; a.z += v.z; a.w += v.w;
    }
    float w = g_invc[comb];
    a.x *= w; a.y *= w; a.z *= w; a.w *= w;
    ((float4*)(g_agg + ((size_t)rel * NN + node) * HH))[lane] = a;
}

// ---------------- tf32 tensor-core GEMM, cp.async double-buffered, split-K=2 ------
// gridDim.y = 2: y=0 handles chunks [0,18), y=1 handles [18,36). Partials to g_part.
#define BM 128
#define GBLK ((NN + BM - 1) / BM)
#define APAD 36
#define BPAD 136
#define ASZ (BM * APAD)
#define BSZ (32 * BPAD)
#define GSMEM (2 * (ASZ + BSZ) * 4)

__global__ __launch_bounds__(256) void gemm_kernel(
    const float* __restrict__ X, const float* __restrict__ W,
    const float* __restrict__ root)
{
    extern __shared__ float smem[];
    uint32_t sbase = (uint32_t)__cvta_generic_to_shared(smem);

    int tid  = threadIdx.x;
    int warp = tid >> 5;
    int lane = tid & 31;
    int gID  = lane >> 2;
    int tig  = lane & 3;
    int wrow = (warp & 3) * 32;
    int wcol = (warp >> 2) * 64;
    int m0   = blockIdx.x * BM;
    int kslc = blockIdx.y;             // 0 or 1
    int chLo = kslc * 18;
    int chHi = chLo + 18;
    float* part = g_part[kslc];

    int arow = tid >> 3, aq = (tid & 7) * 4;
    int bkr  = tid >> 5, bnq = (tid & 31) * 4;

    float c[2][8][4];
    #pragma unroll
    for (int mt = 0; mt < 2; mt++)
        #pragma unroll
        for (int nt = 0; nt < 8; nt++)
            #pragma unroll
            for (int q = 0; q < 4; q++) c[mt][nt][q] = 0.f;

    auto stage = [&](int ch, int buf) {
        int rel = ch >> 2, kc = ch & 3;
        const float* Wp   = (rel < RR) ? (W + (size_t)rel * HH * HH) : root;
        const float* Asrc = (rel < RR) ? (g_agg + (size_t)rel * NN * HH) : X;
        uint32_t abase = sbase + (uint32_t)(buf * ASZ) * 4;
        uint32_t bbase = sbase + (uint32_t)(2 * ASZ + buf * BSZ) * 4;
        #pragma unroll
        for (int it = 0; it < 4; it++) {
            int row = arow + it * 32;
            int gm  = m0 + row; if (gm > NN - 1) gm = NN - 1;
            cp16(abase + (uint32_t)(row * APAD + aq) * 4,
                 Asrc + (size_t)gm * HH + kc * 32 + aq);
            int kr = bkr + it * 8;
            cp16(bbase + (uint32_t)(kr * BPAD + bnq) * 4,
                 Wp + (size_t)(kc * 32 + kr) * HH + bnq);
        }
        cp_commit();
    };

    stage(chLo, 0);

    for (int ch = chLo; ch < chHi; ch++) {
        int buf = (ch - chLo) & 1;
        if (ch < chHi - 1) { stage(ch + 1, buf ^ 1); cp_wait<1>(); }
        else               { cp_wait<0>(); }
        __syncthreads();

        const float* As = smem + buf * ASZ;
        const float* Bs = smem + 2 * ASZ + buf * BSZ;

        #pragma unroll
        for (int ks = 0; ks < 4; ks++) {
            int kb = ks * 8;
            unsigned b[8][2];
            #pragma unroll
            for (int nt = 0; nt < 8; nt++) {
                int col = wcol + nt * 8 + gID;
                b[nt][0] = __float_as_uint(Bs[(kb + tig) * BPAD + col]);
                b[nt][1] = __float_as_uint(Bs[(kb + tig + 4) * BPAD + col]);
            }
            unsigned a[2][4];
            #pragma unroll
            for (int mt = 0; mt < 2; mt++) {
                int r = wrow + mt * 16 + gID;
                a[mt][0] = __float_as_uint(As[r * APAD + kb + tig]);
                a[mt][1] = __float_as_uint(As[(r + 8) * APAD + kb + tig]);
                a[mt][2] = __float_as_uint(As[r * APAD + kb + tig + 4]);
                a[mt][3] = __float_as_uint(As[(r + 8) * APAD + kb + tig + 4]);
            }
            #pragma unroll
            for (int mt = 0; mt < 2; mt++)
                #pragma unroll
                for (int nt = 0; nt < 8; nt++)
                    mma_tf32(c[mt][nt], a[mt], b[nt]);
        }
        __syncthreads();
    }

    // epilogue: raw partials (bias/relu applied in combine_kernel)
    #pragma unroll
    for (int mt = 0; mt < 2; mt++) {
        int r0 = m0 + wrow + mt * 16 + gID;
        int r1 = r0 + 8;
        #pragma unroll
        for (int nt = 0; nt < 8; nt++) {
            int col = wcol + nt * 8 + 2 * tig;
            if (r0 < NN) *(float2*)(part + (size_t)r0 * HH + col)
                             = make_float2(c[mt][nt][0], c[mt][nt][1]);
            if (r1 < NN) *(float2*)(part + (size_t)r1 * HH + col)
                             = make_float2(c[mt][nt][2], c[mt][nt][3]);
        }
    }
}

// ---------------- combine split-K partials: out = relu?(p0 + p1 + bias) -----------
#define CMB_N ((NN * HH) / 4)
__global__ void combine_kernel(const float* __restrict__ bias,
                               float* __restrict__ out, int do_relu) {
    int i = blockIdx.x * blockDim.x + threadIdx.x;
    if (i >= CMB_N) return;
    float4 a = ((const float4*)g_part[0])[i];
    float4 b = ((const float4*)g_part[1])[i];
    int col = (i * 4) & (HH - 1);
    float4 bv = *(const float4*)(bias + col);
    float4 o;
    o.x = a.x + b.x + bv.x;
    o.y = a.y + b.y + bv.y;
    o.z = a.z + b.z + bv.z;
    o.w = a.w + b.w + bv.w;
    if (do_relu) {
        o.x = fmaxf(o.x, 0.f); o.y = fmaxf(o.y, 0.f);
        o.z = fmaxf(o.z, 0.f); o.w = fmaxf(o.w, 0.f);
    }
    ((float4*)out)[i] = o;
}

// ---------------- collapsed layer-2: all 9 column sums in ONE pass over hB --------
#define WS_BLOCKS 148
__global__ void wsum_kernel(const float* __restrict__ hB) {
    __shared__ float sw[256 * RR];
    int tid = threadIdx.x;             // 128 threads = columns
    int rowsPer = (NN + gridDim.x - 1) / gridDim.x;
    int r0 = blockIdx.x * rowsPer;
    int r1 = min(NN, r0 + rowsPer);

    float acc[9];
    #pragma unroll
    for (int s = 0; s < 9; s++) acc[s] = 0.f;

    for (int base = r0; base < r1; base += 256) {
        int nrows = min(256, r1 - base);
        for (int idx = tid * 4; idx < nrows * RR; idx += 128 * 4)
            *(float4*)&sw[idx] = *(const float4*)&g_wgt[base * RR + idx];
        __syncthreads();
        for (int j = 0; j < nrows; j++) {
            float v = hB[(size_t)(base + j) * HH + tid];
            acc[8] += v;
            #pragma unroll
            for (int r = 0; r < RR; r++) acc[r] += sw[j * RR + r] * v;
        }
        __syncthreads();
    }
    #pragma unroll
    for (int s = 0; s < 9; s++) atomicAdd(&g_m[s * HH + tid], acc[s]);
}

// ---------------- layer-3 GEMV (9 blocks): u += (1/N) * m_slot @ W_slot ----------
__global__ void gemv_kernel(const float* __restrict__ W, const float* __restrict__ root,
                            float* __restrict__ uo) {
    int slot = blockIdx.x;
    int tid = threadIdx.x;             // 128
    const float* Wp = (slot < RR) ? (W + (size_t)slot * HH * HH) : root;
    __shared__ float m[HH];
    m[tid] = g_m[slot * HH + tid];
    __syncthreads();
    float acc = 0.f;
    #pragma unroll 8
    for (int k = 0; k < HH; k++)
        acc += m[k] * Wp[k * HH + tid];
    atomicAdd(&uo[tid], acc * (1.0f / (float)NN));
}

// ---------------- final MLP head (bias of layer-3 folded in here) ----------------
__global__ void fcl_kernel(const float* __restrict__ bias2,
                           const float* __restrict__ fc1w, const float* __restrict__ fc1b,
                           const float* __restrict__ fc2w, const float* __restrict__ fc2b,
                           float* __restrict__ out) {
    __shared__ float h[2 * HH];
    __shared__ float red[HH];
    int tid = threadIdx.x;
    if (tid < 2 * HH) h[tid] = g_u[tid] + bias2[tid & 127];
    __syncthreads();
    if (tid < HH) {
        float y = fc1b[tid];
        for (int k = 0; k < 2 * HH; k++) y += h[k] * fc1w[k * HH + tid];
        y = fmaxf(y, 0.f);
        red[tid] = y * fc2w[tid];
    }
    __syncthreads();
    for (int off = 64; off > 0; off >>= 1) {
        if (tid < off) red[tid] += red[tid + off];
        __syncthreads();
    }
    if (tid == 0) out[0] = red[0] + fc2b[0];
}

// ---------------- host orchestration (single stream, round-10 structure) ----------
extern "C" void kernel_launch(void* const* d_in, const int* in_sizes, int n_in,
                              void* d_out, int out_size) {
    const float* x1  = (const float*)d_in[0];
    const int*   ei1 = (const int*)d_in[1];
    const int*   et1 = (const int*)d_in[2];
    const float* x2  = (const float*)d_in[3];
    const int*   ei2 = (const int*)d_in[4];
    const int*   et2 = (const int*)d_in[5];
    const float* Wl[3]    = {(const float*)d_in[6],  (const float*)d_in[9],  (const float*)d_in[12]};
    const float* rootl[3] = {(const float*)d_in[7],  (const float*)d_in[10], (const float*)d_in[13]};
    const float* biasl[3] = {(const float*)d_in[8],  (const float*)d_in[11], (const float*)d_in[14]};
    const float* fc1w = (const float*)d_in[15];
    const float* fc1b = (const float*)d_in[16];
    const float* fc2w = (const float*)d_in[17];
    const float* fc2b = (const float*)d_in[18];

    static int init = 0;
    if (!init) {
        cudaFuncSetAttribute(gemm_kernel, cudaFuncAttributeMaxDynamicSharedMemorySize, GSMEM);
        init = 1;
    }

    void *cnt_p, *bsum_p, *wgt_p, *m_p, *u_p, *hA_p, *hB_p;
    cudaGetSymbolAddress(&cnt_p, g_cnt);
    cudaGetSymbolAddress(&bsum_p, g_bsum);
    cudaGetSymbolAddress(&wgt_p, g_wgt);
    cudaGetSymbolAddress(&m_p, g_m);
    cudaGetSymbolAddress(&u_p, g_u);
    cudaGetSymbolAddress(&hA_p, g_hA);
    cudaGetSymbolAddress(&hB_p, g_hB);
    float* hA = (float*)hA_p;
    float* hB = (float*)hB_p;
    float* u  = (float*)u_p;

    const float* xs[2]  = {x1, x2};
    const int*   eis[2] = {ei1, ei2};
    const int*   ets[2] = {et1, et2};

    int aggBlocks = (NN * RR * 32 + 255) / 256;
    int eBlocks   = (EE + 255) / 256;
    int cBlocks   = (CMB_N + 255) / 256;
    dim3 gemmGrid(GBLK, 2);

    cudaMemsetAsync(u_p, 0, 2 * HH * sizeof(float));

    for (int g = 0; g < 2; g++) {
        cudaMemsetAsync(cnt_p, 0, NN * RR * sizeof(int));
        cudaMemsetAsync(bsum_p, 0, SNB * sizeof(int));
        cudaMemsetAsync(wgt_p, 0, NN * RR * sizeof(float));
        cudaMemsetAsync(m_p, 0, 9 * HH * sizeof(float));

        hist_kernel<<<eBlocks, 256>>>(eis[g], ets[g]);
        expand_kernel<<<SNB, 256>>>();
        scatter_kernel<<<eBlocks, 256>>>(eis[g], ets[g]);   // also accumulates g_wgt

        // layer 0: x -> hA
        agg_kernel<<<aggBlocks, 256>>>(xs[g]);
        gemm_kernel<<<gemmGrid, 256, GSMEM>>>(xs[g], Wl[0], rootl[0]);
        combine_kernel<<<cBlocks, 256>>>(biasl[0], hA, 1);
        // layer 1: hA -> hB
        agg_kernel<<<aggBlocks, 256>>>(hA);
        gemm_kernel<<<gemmGrid, 256, GSMEM>>>(hA, Wl[1], rootl[1]);
        combine_kernel<<<cBlocks, 256>>>(biasl[1], hB, 1);
        // layers 2+3 collapsed: weighted column sums of hB, then GEMV
        wsum_kernel<<<WS_BLOCKS, 128>>>(hB);
        gemv_kernel<<<9, 128>>>(Wl[2], rootl[2], u + g * HH);
    }

    fcl_kernel<<<1, 256>>>(biasl[2], fc1w, fc1b, fc2w, fc2b, (float*)d_out);
}

// round 17
// speedup vs baseline: 1.2794x; 1.2454x over previous
#include <cuda_runtime.h>
#include <cuda_fp16.h>
#include <cstdint>

#define NN 50000
#define EE 800000
#define HH 128
#define RR 8
#define SNB 196                       // ceil(NN/256) node blocks

// ---------------- scratch (device globals; no allocation allowed) ----------------
__device__ __align__(16) __half g_aggh[(size_t)RR * NN * HH]; // fp16 per-rel neighbor means
__device__ __align__(16) __half g_xh[(size_t)NN * HH];        // fp16 copy of layer input x
__device__ __align__(16) __half g_hA[(size_t)NN * HH];
__device__ __align__(16) __half g_hB[(size_t)NN * HH];
__device__ __align__(16) __half g_wt[2 * 9 * HH * HH];        // fp16 transposed weights [l][mat][n][k]
__device__ int   g_cnt[NN * RR];
__device__ float g_invc[NN * RR];
__device__ int   g_beg[NN * RR];
__device__ int   g_cur[NN * RR];
__device__ int   g_bsum[SNB];
__device__ int   g_ep[EE];            // src node id, CSR-sorted by (dst, etype)
__device__ float g_wgt[NN * RR];      // w_r[j] = sum over edges (j->n, type r) of invc[n,r]
__device__ float g_m[9 * HH];         // column sums: slots 0..7 weighted, 8 = plain hB sum
__device__ float g_u[2 * HH];         // final per-graph embeddings (pre-bias)

// ---------------- fp16 mma, fp32 accumulate ----------------
__device__ __forceinline__ void mma_f16(float* c, const unsigned* a, const unsigned* b) {
    asm volatile(
        "mma.sync.aligned.m16n8k16.row.col.f32.f16.f16.f32 "
        "{%0,%1,%2,%3}, {%4,%5,%6,%7}, {%8,%9}, {%0,%1,%2,%3};"
        : "+f"(c[0]), "+f"(c[1]), "+f"(c[2]), "+f"(c[3])
        : "r"(a[0]), "r"(a[1]), "r"(a[2]), "r"(a[3]), "r"(b[0]), "r"(b[1]));
}

// ---------------- cp.async helpers ----------------
__device__ __forceinline__ void cp16(uint32_t saddr, const void* gaddr) {
    asm volatile("cp.async.cg.shared.global [%0], [%1], 16;" :: "r"(saddr), "l"(gaddr));
}
__device__ __forceinline__ void cp_commit() {
    asm volatile("cp.async.commit_group;");
}
template <int N>
__device__ __forceinline__ void cp_wait() {
    asm volatile("cp.async.wait_group %0;" :: "n"(N));
}

// ---------------- one-time weight transpose+convert: W[k][n] -> fp16 Wt[n][k] -----
__global__ void wtrans_kernel(const float* __restrict__ W0, const float* __restrict__ r0,
                              const float* __restrict__ W1, const float* __restrict__ r1) {
    int idx = blockIdx.x * blockDim.x + threadIdx.x;
    if (idx >= 2 * 9 * HH * HH) return;
    int l   = idx / (9 * HH * HH);
    int rem = idx - l * 9 * HH * HH;
    int mat = rem / (HH * HH);
    int e   = rem - mat * HH * HH;
    int n   = e / HH;
    int k   = e - n * HH;
    const float* Wp = (mat < RR) ? ((l == 0 ? W0 : W1) + (size_t)mat * HH * HH)
                                 : (l == 0 ? r0 : r1);
    g_wt[idx] = __float2half_rn(Wp[k * HH + n]);
}

// ---------------- x fp32 -> fp16 ----------------
__global__ void convx_kernel(const float* __restrict__ X, __half* __restrict__ Xh) {
    int i = blockIdx.x * blockDim.x + threadIdx.x;
    if (i >= NN * HH / 4) return;
    float4 v = ((const float4*)X)[i];
    __half2 h0 = __floats2half2_rn(v.x, v.y);
    __half2 h1 = __floats2half2_rn(v.z, v.w);
    uint2 u;
    u.x = *(unsigned*)&h0;
    u.y = *(unsigned*)&h1;
    ((uint2*)Xh)[i] = u;
}

// ---------------- preprocessing ----------------
__global__ void hist_kernel(const int* __restrict__ ei, const int* __restrict__ et) {
    int e = blockIdx.x * blockDim.x + threadIdx.x;
    if (e < EE) {
        int dst = ei[EE + e];
        int r = et[e];
        atomicAdd(&g_cnt[dst * RR + r], 1);
        atomicAdd(&g_bsum[dst >> 8], 1);
    }
}

__global__ void expand_kernel() {
    __shared__ int sh[256];
    __shared__ int s_base;
    int b = blockIdx.x;
    int tid = threadIdx.x;

    sh[tid] = (tid < b) ? g_bsum[tid] : 0;
    __syncthreads();
    for (int off = 128; off > 0; off >>= 1) {
        if (tid < off) sh[tid] += sh[tid + off];
        __syncthreads();
    }
    if (tid == 0) s_base = sh[0];
    __syncthreads();

    int i = b * 256 + tid;
    int cv[RR];
    int d = 0;
    if (i < NN) {
        int4 c0 = *(const int4*)&g_cnt[i * RR];
        int4 c1 = *(const int4*)&g_cnt[i * RR + 4];
        cv[0] = c0.x; cv[1] = c0.y; cv[2] = c0.z; cv[3] = c0.w;
        cv[4] = c1.x; cv[5] = c1.y; cv[6] = c1.z; cv[7] = c1.w;
        #pragma unroll
        for (int r = 0; r < RR; r++) d += cv[r];
    }
    sh[tid] = d;
    __syncthreads();
    for (int off = 1; off < 256; off <<= 1) {
        int t = (tid >= off) ? sh[tid - off] : 0;
        __syncthreads();
        sh[tid] += t;
        __syncthreads();
    }
    if (i < NN) {
        int c0 = s_base + sh[tid] - d;
        #pragma unroll
        for (int r = 0; r < RR; r++) {
            g_beg[i * RR + r] = c0;
            g_cur[i * RR + r] = c0;
            g_invc[i * RR + r] = 1.0f / (float)(cv[r] > 0 ? cv[r] : 1);
            c0 += cv[r];
        }
    }
}

__global__ void scatter_kernel(const int* __restrict__ ei, const int* __restrict__ et) {
    int e = blockIdx.x * blockDim.x + threadIdx.x;
    if (e < EE) {
        int src = ei[e];
        int dst = ei[EE + e];
        int r = et[e];
        int pos = atomicAdd(&g_cur[dst * RR + r], 1);
        g_ep[pos] = src;
        atomicAdd(&g_wgt[src * RR + r], g_invc[dst * RR + r]);
    }
}

// ---------------- aggregation: warp per (rel,node), fp16 in/out, fp32 accumulate --
__global__ void agg_kernel(const __half* __restrict__ Xh) {
    int gw = (blockIdx.x * blockDim.x + threadIdx.x) >> 5;
    int lane = threadIdx.x & 31;
    if (gw >= NN * RR) return;
    int rel = gw / NN;
    int node = gw - rel * NN;

    int comb = node * RR + rel;
    int b = g_beg[comb];
    int c = g_cnt[comb];
    float4 a = make_float4(0.f, 0.f, 0.f, 0.f);
    for (int e = b; e < b + c; e++) {
        int src = g_ep[e];
        uint2 u = ((const uint2*)(Xh + (size_t)src * HH))[lane];
        float2 f0 = __half22float2(*(__half2*)&u.x);
        float2 f1 = __half22float2(*(__half2*)&u.y);
        a.x += f0.x; a.y += f0.y; a.z += f1.x; a.w += f1.y;
    }
    float w = g_invc[comb];
    __half2 h0 = __floats2half2_rn(a.x * w, a.y * w);
    __half2 h1 = __floats2half2_rn(a.z * w, a.w * w);
    uint2 o;
    o.x = *(unsigned*)&h0;
    o.y = *(unsigned*)&h1;
    ((uint2*)(g_aggh + ((size_t)rel * NN + node) * HH))[lane] = o;
}

// ---------------- fp16 tensor-core GEMM, cp.async double-buffered -----------------
// out[N,128] = relu?( sum_r A_r @ W_r + X @ root + bias ); K = 9*128 in 36 chunks.
// 128x128 CTA tile, 8 warps 4x2 (warp 32x64), m16n8k16, fp32 accum, fp16 out.
#define BM 128
#define GBLK ((NN + BM - 1) / BM)
#define APADH 40                       // halves; stride 80B -> conflict-free frags
#define ABH (128 * APADH)              // halves per (A or B) buffer
#define GSMEM (4 * ABH * 2)            // bytes: As0|As1|Bs0|Bs1

__global__ __launch_bounds__(256) void gemm_kernel(
    const __half* __restrict__ Xh, const __half* __restrict__ Wt,
    const float* __restrict__ bias, __half* __restrict__ out, int do_relu)
{
    extern __shared__ __half smemh[];
    uint32_t sbase = (uint32_t)__cvta_generic_to_shared(smemh);

    int tid  = threadIdx.x;
    int warp = tid >> 5;
    int lane = tid & 31;
    int gID  = lane >> 2;
    int tig  = lane & 3;
    int wrow = (warp & 3) * 32;
    int wcol = (warp >> 2) * 64;
    int m0   = blockIdx.x * BM;

    float c[2][8][4];
    #pragma unroll
    for (int mt = 0; mt < 2; mt++)
        #pragma unroll
        for (int nt = 0; nt < 8; nt++)
            #pragma unroll
            for (int q = 0; q < 4; q++) c[mt][nt][q] = 0.f;

    auto stage = [&](int ch, int buf) {
        int rel = ch >> 2, kc = ch & 3;
        const __half* Asrc = (rel < RR) ? (g_aggh + (size_t)rel * NN * HH) : Xh;
        const __half* Bsrc = Wt + (size_t)rel * HH * HH;     // [n][k] fp16
        uint32_t abase = sbase + (uint32_t)(buf * ABH) * 2;
        uint32_t bbase = sbase + (uint32_t)((2 + buf) * ABH) * 2;
        #pragma unroll
        for (int t = 0; t < 2; t++) {
            int idx = tid + t * 256;           // 0..511
            int row = idx >> 2;                // 0..127
            int seg = idx & 3;                 // 16B (8-half) segments
            int gm = m0 + row; if (gm > NN - 1) gm = NN - 1;
            cp16(abase + (uint32_t)(row * APADH + seg * 8) * 2,
                 Asrc + (size_t)gm * HH + kc * 32 + seg * 8);
            cp16(bbase + (uint32_t)(row * APADH + seg * 8) * 2,
                 Bsrc + (size_t)row * HH + kc * 32 + seg * 8);
        }
        cp_commit();
    };

    stage(0, 0);

    for (int ch = 0; ch < 36; ch++) {
        int buf = ch & 1;
        if (ch < 35) { stage(ch + 1, buf ^ 1); cp_wait<1>(); }
        else         { cp_wait<0>(); }
        __syncthreads();

        const __half* As = smemh + buf * ABH;
        const __half* Bs = smemh + (2 + buf) * ABH;

        #pragma unroll
        for (int ks = 0; ks < 2; ks++) {
            int kb = ks * 16;
            unsigned a[2][4];
            #pragma unroll
            for (int mt = 0; mt < 2; mt++) {
                int r = wrow + mt * 16 + gID;
                a[mt][0] = *(const unsigned*)&As[r * APADH + kb + 2 * tig];
                a[mt][1] = *(const unsigned*)&As[(r + 8) * APADH + kb + 2 * tig];
                a[mt][2] = *(const unsigned*)&As[r * APADH + kb + 8 + 2 * tig];
                a[mt][3] = *(const unsigned*)&As[(r + 8) * APADH + kb + 8 + 2 * tig];
            }
            unsigned b[8][2];
            #pragma unroll
            for (int nt = 0; nt < 8; nt++) {
                int n = wcol + nt * 8 + gID;
                b[nt][0] = *(const unsigned*)&Bs[n * APADH + kb + 2 * tig];
                b[nt][1] = *(const unsigned*)&Bs[n * APADH + kb + 8 + 2 * tig];
            }
            #pragma unroll
            for (int mt = 0; mt < 2; mt++)
                #pragma unroll
                for (int nt = 0; nt < 8; nt++)
                    mma_f16(c[mt][nt], a[mt], b[nt]);
        }
        __syncthreads();
    }

    // epilogue: bias, relu, fp16 store
    #pragma unroll
    for (int mt = 0; mt < 2; mt++) {
        int r0 = m0 + wrow + mt * 16 + gID;
        int r1 = r0 + 8;
        #pragma unroll
        for (int nt = 0; nt < 8; nt++) {
            int col = wcol + nt * 8 + 2 * tig;
            float b0 = bias[col], b1 = bias[col + 1];
            float v0 = c[mt][nt][0] + b0;
            float v1 = c[mt][nt][1] + b1;
            float v2 = c[mt][nt][2] + b0;
            float v3 = c[mt][nt][3] + b1;
            if (do_relu) {
                v0 = fmaxf(v0, 0.f); v1 = fmaxf(v1, 0.f);
                v2 = fmaxf(v2, 0.f); v3 = fmaxf(v3, 0.f);
            }
            if (r0 < NN) *(__half2*)(out + (size_t)r0 * HH + col) = __floats2half2_rn(v0, v1);
            if (r1 < NN) *(__half2*)(out + (size_t)r1 * HH + col) = __floats2half2_rn(v2, v3);
        }
    }
}

// ---------------- collapsed layer-2: all 9 column sums in ONE pass over hB --------
#define WS_BLOCKS 148
__global__ void wsum_kernel(const __half* __restrict__ hB) {
    __shared__ float sw[256 * RR];
    int tid = threadIdx.x;             // 128 threads = columns
    int rowsPer = (NN + gridDim.x - 1) / gridDim.x;
    int r0 = blockIdx.x * rowsPer;
    int r1 = min(NN, r0 + rowsPer);

    float acc[9];
    #pragma unroll
    for (int s = 0; s < 9; s++) acc[s] = 0.f;

    for (int base = r0; base < r1; base += 256) {
        int nrows = min(256, r1 - base);
        for (int idx = tid * 4; idx < nrows * RR; idx += 128 * 4)
            *(float4*)&sw[idx] = *(const float4*)&g_wgt[base * RR + idx];
        __syncthreads();
        for (int j = 0; j < nrows; j++) {
            float v = __half2float(hB[(size_t)(base + j) * HH + tid]);
            acc[8] += v;
            #pragma unroll
            for (int r = 0; r < RR; r++) acc[r] += sw[j * RR + r] * v;
        }
        __syncthreads();
    }
    #pragma unroll
    for (int s = 0; s < 9; s++) atomicAdd(&g_m[s * HH + tid], acc[s]);
}

// ---------------- layer-3 GEMV (9 blocks): u += (1/N) * m_slot @ W_slot ----------
__global__ void gemv_kernel(const float* __restrict__ W, const float* __restrict__ root,
                            float* __restrict__ uo) {
    int slot = blockIdx.x;
    int tid = threadIdx.x;             // 128
    const float* Wp = (slot < RR) ? (W + (size_t)slot * HH * HH) : root;
    __shared__ float m[HH];
    m[tid] = g_m[slot * HH + tid];
    __syncthreads();
    float acc = 0.f;
    #pragma unroll 8
    for (int k = 0; k < HH; k++)
        acc += m[k] * Wp[k * HH + tid];
    atomicAdd(&uo[tid], acc * (1.0f / (float)NN));
}

// ---------------- final MLP head (bias of layer-3 folded in here) ----------------
__global__ void fcl_kernel(const float* __restrict__ bias2,
                           const float* __restrict__ fc1w, const float* __restrict__ fc1b,
                           const float* __restrict__ fc2w, const float* __restrict__ fc2b,
                           float* __restrict__ out) {
    __shared__ float h[2 * HH];
    __shared__ float red[HH];
    int tid = threadIdx.x;
    if (tid < 2 * HH) h[tid] = g_u[tid] + bias2[tid & 127];
    __syncthreads();
    if (tid < HH) {
        float y = fc1b[tid];
        for (int k = 0; k < 2 * HH; k++) y += h[k] * fc1w[k * HH + tid];
        y = fmaxf(y, 0.f);
        red[tid] = y * fc2w[tid];
    }
    __syncthreads();
    for (int off = 64; off > 0; off >>= 1) {
        if (tid < off) red[tid] += red[tid + off];
        __syncthreads();
    }
    if (tid == 0) out[0] = red[0] + fc2b[0];
}

// ---------------- host orchestration ----------------
extern "C" void kernel_launch(void* const* d_in, const int* in_sizes, int n_in,
                              void* d_out, int out_size) {
    const float* x1  = (const float*)d_in[0];
    const int*   ei1 = (const int*)d_in[1];
    const int*   et1 = (const int*)d_in[2];
    const float* x2  = (const float*)d_in[3];
    const int*   ei2 = (const int*)d_in[4];
    const int*   et2 = (const int*)d_in[5];
    const float* Wl[3]    = {(const float*)d_in[6],  (const float*)d_in[9],  (const float*)d_in[12]};
    const float* rootl[3] = {(const float*)d_in[7],  (const float*)d_in[10], (const float*)d_in[13]};
    const float* biasl[3] = {(const float*)d_in[8],  (const float*)d_in[11], (const float*)d_in[14]};
    const float* fc1w = (const float*)d_in[15];
    const float* fc1b = (const float*)d_in[16];
    const float* fc2w = (const float*)d_in[17];
    const float* fc2b = (const float*)d_in[18];

    static int init = 0;
    if (!init) {
        cudaFuncSetAttribute(gemm_kernel, cudaFuncAttributeMaxDynamicSharedMemorySize, GSMEM);
        init = 1;
    }

    void *cnt_p, *bsum_p, *wgt_p, *m_p, *u_p, *xh_p, *hA_p, *hB_p, *wt_p;
    cudaGetSymbolAddress(&cnt_p, g_cnt);
    cudaGetSymbolAddress(&bsum_p, g_bsum);
    cudaGetSymbolAddress(&wgt_p, g_wgt);
    cudaGetSymbolAddress(&m_p, g_m);
    cudaGetSymbolAddress(&u_p, g_u);
    cudaGetSymbolAddress(&xh_p, g_xh);
    cudaGetSymbolAddress(&hA_p, g_hA);
    cudaGetSymbolAddress(&hB_p, g_hB);
    cudaGetSymbolAddress(&wt_p, g_wt);
    __half* xh = (__half*)xh_p;
    __half* hA = (__half*)hA_p;
    __half* hB = (__half*)hB_p;
    __half* wt = (__half*)wt_p;
    float*  u  = (float*)u_p;

    const float* xs[2]  = {x1, x2};
    const int*   eis[2] = {ei1, ei2};
    const int*   ets[2] = {et1, et2};

    int aggBlocks = (NN * RR * 32 + 255) / 256;
    int eBlocks   = (EE + 255) / 256;
    int cvBlocks  = (NN * HH / 4 + 255) / 256;
    int wtBlocks  = (2 * 9 * HH * HH + 255) / 256;

    cudaMemsetAsync(u_p, 0, 2 * HH * sizeof(float));
    wtrans_kernel<<<wtBlocks, 256>>>(Wl[0], rootl[0], Wl[1], rootl[1]);

    for (int g = 0; g < 2; g++) {
        cudaMemsetAsync(cnt_p, 0, NN * RR * sizeof(int));
        cudaMemsetAsync(bsum_p, 0, SNB * sizeof(int));
        cudaMemsetAsync(wgt_p, 0, NN * RR * sizeof(float));
        cudaMemsetAsync(m_p, 0, 9 * HH * sizeof(float));

        convx_kernel<<<cvBlocks, 256>>>(xs[g], xh);
        hist_kernel<<<eBlocks, 256>>>(eis[g], ets[g]);
        expand_kernel<<<SNB, 256>>>();
        scatter_kernel<<<eBlocks, 256>>>(eis[g], ets[g]);   // also accumulates g_wgt

        // layer 0: xh -> hA (fp16)
        agg_kernel<<<aggBlocks, 256>>>(xh);
        gemm_kernel<<<GBLK, 256, GSMEM>>>(xh, wt, biasl[0], hA, 1);
        // layer 1: hA -> hB (fp16)
        agg_kernel<<<aggBlocks, 256>>>(hA);
        gemm_kernel<<<GBLK, 256, GSMEM>>>(hA, wt + (size_t)9 * HH * HH, biasl[1], hB, 1);
        // layers 2+3 collapsed: weighted column sums of hB, then GEMV (fp32)
        wsum_kernel<<<WS_BLOCKS, 128>>>(hB);
        gemv_kernel<<<9, 128>>>(Wl[2], rootl[2], u + g * HH);
    }

    fcl_kernel<<<1, 256>>>(biasl[2], fc1w, fc1b, fc2w, fc2b, (float*)d_out);
}